// round 11
// baseline (speedup 1.0000x reference)
#include <cuda_runtime.h>
#include <cstdint>

#define B_I   3072
#define N_N   2048
#define H_H   1024
#define M_M   512
#define NITER 100

// bank-conflict padding: one extra float2 per 16
#define NPAD(i) ((i) + ((i) >> 4))
#define BUFSZ 1088   // NPAD(1023)=1086

// twiddle tables
__device__ float2 g_tw[2048];   // e^{-2*pi*i*q/2048}
__device__ float2 g_ph[2048];   // e^{+i*pi*k/4096}

// ---------------------------------------------------------------------------
__device__ __forceinline__ float2 cadd(float2 a, float2 b) {
    return make_float2(a.x + b.x, a.y + b.y);
}
__device__ __forceinline__ float2 csub(float2 a, float2 b) {
    return make_float2(a.x - b.x, a.y - b.y);
}
__device__ __forceinline__ float2 cmulf(float2 a, float2 b) {
    return make_float2(a.x * b.x - a.y * b.y, a.x * b.y + a.y * b.x);
}
template<int DIR>
__device__ __forceinline__ float2 rotd(float2 v) {   // multiply by DIR*i
    return (DIR < 0) ? make_float2(v.y, -v.x) : make_float2(-v.y, v.x);
}

__device__ __forceinline__ int get_idx(const void* idxp, int m) {
    const long long* p64 = (const long long*)idxp;
    if ((p64[0] >> 32) == 0LL) return (int)p64[m];
    return ((const int*)idxp)[m];
}

// ---------------------------------------------------------------------------
template<int DIR>
__device__ __forceinline__ void dif8(const float2 v[8], float2 o[8]) {
    const float r = 0.70710678118654752f;
    float2 s0 = cadd(v[0], v[4]), s1 = cadd(v[1], v[5]);
    float2 s2 = cadd(v[2], v[6]), s3 = cadd(v[3], v[7]);
    float2 d0 = csub(v[0], v[4]);
    float2 d1 = csub(v[1], v[5]);
    float2 d2 = csub(v[2], v[6]);
    float2 d3 = csub(v[3], v[7]);
    if (DIR < 0) {
        d1 = make_float2(r * (d1.x + d1.y), r * (d1.y - d1.x));
        d2 = make_float2(d2.y, -d2.x);
        d3 = make_float2(r * (d3.y - d3.x), -r * (d3.x + d3.y));
    } else {
        d1 = make_float2(r * (d1.x - d1.y), r * (d1.y + d1.x));
        d2 = make_float2(-d2.y, d2.x);
        d3 = make_float2(-r * (d3.x + d3.y), r * (d3.x - d3.y));
    }
    float2 a0 = cadd(s0, s2), b0 = csub(s0, s2);
    float2 a1 = cadd(s1, s3), b1 = rotd<DIR>(csub(s1, s3));
    o[0] = cadd(a0, a1);
    o[4] = csub(a0, a1);
    o[2] = cadd(b0, b1);
    o[6] = csub(b0, b1);
    float2 c0 = cadd(d0, d2), e0 = csub(d0, d2);
    float2 c1 = cadd(d1, d3), e1 = rotd<DIR>(csub(d1, d3));
    o[1] = cadd(c0, c1);
    o[5] = csub(c0, c1);
    o[3] = cadd(e0, e1);
    o[7] = csub(e0, e1);
}

template<int DIR>
__device__ __forceinline__ void dif4(const float2 v[4], float2 o[4]) {
    float2 a0 = cadd(v[0], v[2]), b0 = csub(v[0], v[2]);
    float2 a1 = cadd(v[1], v[3]), b1 = rotd<DIR>(csub(v[1], v[3]));
    o[0] = cadd(a0, a1);
    o[2] = csub(a0, a1);
    o[1] = cadd(b0, b1);
    o[3] = csub(b0, b1);
}

// W16^e multiply (forward table; DIR>0 conjugates).  e in {0,1,2,3,4,6,9}.
template<int DIR>
__device__ __forceinline__ float2 w16mul(float2 a, int e) {
    const float C1 = 0.92387953251128675f, S1 = 0.38268343236508977f;
    const float R_ = 0.70710678118654752f;
    float c, s;
    switch (e) {
        case 0: return a;
        case 1: c =  C1; s = -S1; break;
        case 2: c =  R_; s = -R_; break;
        case 3: c =  S1; s = -C1; break;
        case 4: c = 0.f; s = -1.f; break;
        case 6: c = -R_; s = -R_; break;
        default: c = -C1; s =  S1; break;   // e == 9
    }
    if (DIR > 0) s = -s;
    return make_float2(a.x * c - a.y * s, a.x * s + a.y * c);
}

// DFT-16 natural order via two radix-4 layers: x[n], n=r+4m;
// X[q+4p] = DFT4_p( W16^{rq} * DFT4_q(x[r+4m]) ).
template<int DIR>
__device__ __forceinline__ void dif16(const float2 v[16], float2 o[16]) {
    float2 T[16];
    #pragma unroll
    for (int r = 0; r < 4; r++) {
        float2 in4[4] = { v[r], v[r + 4], v[r + 8], v[r + 12] };
        float2 t4[4];
        dif4<DIR>(in4, t4);
        T[r * 4 + 0] = t4[0]; T[r * 4 + 1] = t4[1];
        T[r * 4 + 2] = t4[2]; T[r * 4 + 3] = t4[3];
    }
    #pragma unroll
    for (int q = 0; q < 4; q++) {
        float2 u[4];
        u[0] = T[q];
        u[1] = w16mul<DIR>(T[4 + q], q);
        u[2] = w16mul<DIR>(T[8 + q], 2 * q);
        u[3] = w16mul<DIR>(T[12 + q], 3 * q);
        float2 x4[4];
        dif4<DIR>(u, x4);
        #pragma unroll
        for (int p = 0; p < 4; p++) o[q + 4 * p] = x4[p];
    }
}

// ---------------------------------------------------------------------------
// Stockham stage, 1024-pt, out-of-place; radix 4/8/16.
// ---------------------------------------------------------------------------
template<int R, int Ns, int DIR>
__device__ __forceinline__ void fft_stage(const float2* __restrict__ in,
                                          float2* __restrict__ out, int tid) {
    constexpr int NB  = H_H / R;
    constexpr int TWF = 2048 / (Ns * R);
    constexpr int ITER = (NB + 127) / 128;
    #pragma unroll
    for (int jj = 0; jj < ITER; jj++) {
        const int j = tid + jj * 128;
        if (NB < 128 && j >= NB) break;
        float2 v[R];
        #pragma unroll
        for (int t = 0; t < R; t++) v[t] = in[NPAD(j + t * NB)];
        if (Ns > 1) {
            const int q0 = (j & (Ns - 1)) * TWF;
            #pragma unroll
            for (int t = 1; t < R; t++) {
                float2 w = g_tw[t * q0];
                if (DIR > 0) w.y = -w.y;
                v[t] = cmulf(v[t], w);
            }
        }
        float2 o[R];
        if (R == 16) dif16<DIR>(v, o);
        else if (R == 8) dif8<DIR>(v, o);
        else dif4<DIR>(v, o);
        const int idxD = (j / Ns) * (Ns * R) + (j & (Ns - 1));
        #pragma unroll
        for (int t = 0; t < R; t++) out[NPAD(idxD + t * Ns)] = o[t];
    }
}

// ---------------------------------------------------------------------------
__global__ void k_build_tw() {
    int q = blockIdx.x * blockDim.x + threadIdx.x;
    if (q < 2048) {
        float a = (float)q * (1.0f / 1024.0f);
        g_tw[q] = make_float2(cospif(a), -sinpif(a));
        float p = (float)q * (1.0f / 4096.0f);
        g_ph[q] = make_float2(cospif(p), sinpif(p));
    }
}

// ---------------------------------------------------------------------------
#define C_K0  0.0220970869120796f   // 1/sqrt(2048)
#define C_KS  0.015625f             // 1/64
#define W_0   0.0220970869120796f
#define W_K   0.03125f
#define SQRT2 1.41421356237309505f

// packed idct spectrum element, computed straight from sarr
__device__ __forceinline__ float2 zval(const float* __restrict__ sarr, int q) {
    float2 Vq, Vh;
    if (q == 0) {
        Vq = make_float2(sarr[0] * C_K0, 0.0f);
        Vh = make_float2(SQRT2 * sarr[H_H] * C_KS, 0.0f);
    } else {
        float Xq  = sarr[q] * C_KS;
        float Xnq = sarr[N_N - q] * C_KS;
        float2 p  = g_ph[q];
        Vq = make_float2(p.x * Xq + p.y * Xnq, p.y * Xq - p.x * Xnq);
        float Xh  = sarr[q + H_H] * C_KS;
        float Xhq = sarr[H_H - q] * C_KS;
        float2 p2 = g_ph[q + H_H];
        Vh = make_float2(p2.x * Xh + p2.y * Xhq, p2.y * Xh - p2.x * Xhq);
    }
    float2 sum = cadd(Vq, Vh);
    float2 dif = csub(Vq, Vh);
    float2 tw  = g_tw[q];
    float2 e   = make_float2(tw.x * dif.x + tw.y * dif.y,
                             tw.x * dif.y - tw.y * dif.x);   // conj(tw)*dif
    return make_float2(sum.x - e.y, sum.y + e.x);            // sum + i*e
}

// IFFT stage 1 (R=8, Ns=1, DIR=+1) fused with Z construction
__device__ __forceinline__ void ifft_stage1_fromS(const float* __restrict__ sarr,
                                                  float2* __restrict__ out, int tid) {
    float2 v[8];
    #pragma unroll
    for (int t = 0; t < 8; t++) v[t] = zval(sarr, tid + t * 128);
    float2 o[8];
    dif8<1>(v, o);
    const int idxD = tid * 8;
    #pragma unroll
    for (int t = 0; t < 8; t++) out[NPAD(idxD + t)] = o[t];
}

// ---------------------------------------------------------------------------
__global__ void __launch_bounds__(128) solver(
    const float* __restrict__ x, const void* __restrict__ idxs,
    float* __restrict__ out)
{
    __shared__ float2 bufA[BUFSZ];
    __shared__ float2 bufB[BUFSZ];
    __shared__ float2 bufC[BUFSZ];   // scatter-only buffer: zeroed ONCE
    __shared__ float  sarr[N_N];

    const int tid = threadIdx.x;
    const int sig = blockIdx.x;
    const float* xs = x + (size_t)sig * N_N;

    // per-thread measurement registers + one-time bufC zero + s=0
    int   nmr[4];
    float bmr[4];
    #pragma unroll
    for (int u = 0; u < 4; u++) {
        int m = tid + u * 128;
        int j = get_idx(idxs, m);
        bmr[u] = xs[j] * 100.0f;
        nmr[u] = (j & 1) ? (2047 - ((j - 1) >> 1)) : (j >> 1);
    }
    for (int i = tid; i < BUFSZ; i += 128) bufC[i] = make_float2(0.f, 0.f);
    for (int k = tid; k < N_N; k += 128) sarr[k] = 0.0f;
    __syncthreads();

    for (int it = 0; it < NITER; it++) {
        // ---- idct (IFFT, 3 stages; stage 1 fused with Z build) ----
        ifft_stage1_fromS(sarr, bufA, tid);     __syncthreads();
        fft_stage<8, 8, 1>(bufA, bufB, tid);    __syncthreads();
        fft_stage<16, 64, 1>(bufB, bufA, tid);  __syncthreads();
        // z in bufA

        // ---- gather residual; scatter into always-clean bufC ----
        #pragma unroll
        for (int u = 0; u < 4; u++) {
            int p = nmr[u];
            float2 zv = bufA[NPAD(p >> 1)];
            float r = ((p & 1) ? zv.y : zv.x) - bmr[u];
            ((float*)bufC)[2 * NPAD(p >> 1) + (p & 1)] = r;
        }
        __syncthreads();

        // ---- dct (forward FFT, 3 stages) ----
        fft_stage<8, 1, -1>(bufC, bufA, tid);   __syncthreads();
        fft_stage<8, 8, -1>(bufA, bufB, tid);   __syncthreads();
        fft_stage<16, 64, -1>(bufB, bufA, tid); __syncthreads();
        // spectrum in bufA

        // ---- unpack + dct post + ISTA update (pairs k=q, N-q) ----
        for (int q = tid; q < H_H; q += 128) {
            if (q == 0) {
                float2 Z0 = bufA[NPAD(0)];
                float v0 = Z0.x + Z0.y;
                float vh = Z0.x - Z0.y;
                float g0 = W_0 * v0;
                float gh = W_K * (g_ph[H_H].x * vh);
                float u0 = sarr[0] - g0;
                float t0 = fabsf(u0) - 0.05f;
                sarr[0] = (t0 > 0.0f) ? copysignf(t0, u0) : 0.0f;
                float uh = sarr[H_H] - gh;
                float th = fabsf(uh) - 0.05f;
                sarr[H_H] = (th > 0.0f) ? copysignf(th, uh) : 0.0f;
            } else {
                float2 Zq = bufA[NPAD(q)];
                float2 Zr = bufA[NPAD(H_H - q)];
                float2 Zm = make_float2(Zr.x, -Zr.y);
                float2 Es = make_float2(0.5f * (Zq.x + Zm.x),
                                        0.5f * (Zq.y + Zm.y));
                float2 Os = csub(Zq, Zm);
                float2 t  = cmulf(g_tw[q], Os);
                float2 V  = make_float2(Es.x + 0.5f * t.y,
                                        Es.y - 0.5f * t.x);
                float2 p1 = g_ph[q];
                float Xq  = p1.x * V.x + p1.y * V.y;
                float2 p2 = g_ph[N_N - q];
                float Xnq = p2.x * V.x - p2.y * V.y;
                float uq = sarr[q] - W_K * Xq;
                float tq = fabsf(uq) - 0.05f;
                sarr[q] = (tq > 0.0f) ? copysignf(tq, uq) : 0.0f;
                float un = sarr[N_N - q] - W_K * Xnq;
                float tn = fabsf(un) - 0.05f;
                sarr[N_N - q] = (tn > 0.0f) ? copysignf(tn, un) : 0.0f;
            }
        }
        __syncthreads();
    }

    // ---- final: y = idct(s) / 100 ----
    ifft_stage1_fromS(sarr, bufA, tid);     __syncthreads();
    fft_stage<8, 8, 1>(bufA, bufB, tid);    __syncthreads();
    fft_stage<16, 64, 1>(bufB, bufA, tid);  __syncthreads();

    float* os = out + (size_t)sig * N_N;
    for (int j = tid; j < N_N; j += 128) {
        float2 zv = bufA[NPAD(j >> 1)];
        float v = (j & 1) ? zv.y : zv.x;
        int o = (j < H_H) ? (2 * j) : (2 * (2047 - j) + 1);
        os[o] = v * 0.01f;
    }
}

extern "C" void kernel_launch(void* const* d_in, const int* in_sizes, int n_in,
                              void* d_out, int out_size) {
    const float* x    = (const float*)d_in[0];
    const void*  idxs = d_in[1];
    float*       out  = (float*)d_out;

    k_build_tw<<<(2048 + 255) / 256, 256>>>();
    solver<<<B_I, 128>>>(x, idxs, out);
}

// round 12
// speedup vs baseline: 1.5133x; 1.5133x over previous
#include <cuda_runtime.h>
#include <cstdint>

#define B_I   3072
#define N_N   2048
#define H_H   1024
#define M_M   512
#define NITER 100

// bank-conflict padding: one extra float2 per 16
#define NPAD(i) ((i) + ((i) >> 4))
#define BUFSZ 1088   // NPAD(1023)=1086

// twiddle tables
__device__ float2 g_tw[2048];   // e^{-2*pi*i*q/2048}
__device__ float2 g_ph[2048];   // e^{+i*pi*k/4096}

// ---------------------------------------------------------------------------
__device__ __forceinline__ float2 cadd(float2 a, float2 b) {
    return make_float2(a.x + b.x, a.y + b.y);
}
__device__ __forceinline__ float2 csub(float2 a, float2 b) {
    return make_float2(a.x - b.x, a.y - b.y);
}
__device__ __forceinline__ float2 cmulf(float2 a, float2 b) {
    return make_float2(a.x * b.x - a.y * b.y, a.x * b.y + a.y * b.x);
}
template<int DIR>
__device__ __forceinline__ float2 rotd(float2 v) {   // multiply by DIR*i
    return (DIR < 0) ? make_float2(v.y, -v.x) : make_float2(-v.y, v.x);
}

__device__ __forceinline__ int get_idx(const void* idxp, int m) {
    const long long* p64 = (const long long*)idxp;
    if ((p64[0] >> 32) == 0LL) return (int)p64[m];
    return ((const int*)idxp)[m];
}

// ---------------------------------------------------------------------------
template<int DIR>
__device__ __forceinline__ void dif8(const float2 v[8], float2 o[8]) {
    const float r = 0.70710678118654752f;
    float2 s0 = cadd(v[0], v[4]), s1 = cadd(v[1], v[5]);
    float2 s2 = cadd(v[2], v[6]), s3 = cadd(v[3], v[7]);
    float2 d0 = csub(v[0], v[4]);
    float2 d1 = csub(v[1], v[5]);
    float2 d2 = csub(v[2], v[6]);
    float2 d3 = csub(v[3], v[7]);
    if (DIR < 0) {
        d1 = make_float2(r * (d1.x + d1.y), r * (d1.y - d1.x));
        d2 = make_float2(d2.y, -d2.x);
        d3 = make_float2(r * (d3.y - d3.x), -r * (d3.x + d3.y));
    } else {
        d1 = make_float2(r * (d1.x - d1.y), r * (d1.y + d1.x));
        d2 = make_float2(-d2.y, d2.x);
        d3 = make_float2(-r * (d3.x + d3.y), r * (d3.x - d3.y));
    }
    float2 a0 = cadd(s0, s2), b0 = csub(s0, s2);
    float2 a1 = cadd(s1, s3), b1 = rotd<DIR>(csub(s1, s3));
    o[0] = cadd(a0, a1);
    o[4] = csub(a0, a1);
    o[2] = cadd(b0, b1);
    o[6] = csub(b0, b1);
    float2 c0 = cadd(d0, d2), e0 = csub(d0, d2);
    float2 c1 = cadd(d1, d3), e1 = rotd<DIR>(csub(d1, d3));
    o[1] = cadd(c0, c1);
    o[5] = csub(c0, c1);
    o[3] = cadd(e0, e1);
    o[7] = csub(e0, e1);
}

template<int DIR>
__device__ __forceinline__ void dif4(const float2 v[4], float2 o[4]) {
    float2 a0 = cadd(v[0], v[2]), b0 = csub(v[0], v[2]);
    float2 a1 = cadd(v[1], v[3]), b1 = rotd<DIR>(csub(v[1], v[3]));
    o[0] = cadd(a0, a1);
    o[2] = csub(a0, a1);
    o[1] = cadd(b0, b1);
    o[3] = csub(b0, b1);
}

// ---------------------------------------------------------------------------
// Stockham autosort stage, 1024-pt, out-of-place; radix 4/8.
// ---------------------------------------------------------------------------
template<int R, int Ns, int DIR>
__device__ __forceinline__ void fft_stage(const float2* __restrict__ in,
                                          float2* __restrict__ out, int tid) {
    constexpr int NB  = H_H / R;
    constexpr int TWF = 2048 / (Ns * R);
    #pragma unroll
    for (int jj = 0; jj < NB / 128; jj++) {
        const int j = tid + jj * 128;
        float2 v[R];
        #pragma unroll
        for (int t = 0; t < R; t++) v[t] = in[NPAD(j + t * NB)];
        if (Ns > 1) {
            const int q0 = (j & (Ns - 1)) * TWF;
            #pragma unroll
            for (int t = 1; t < R; t++) {
                float2 w = g_tw[t * q0];
                if (DIR > 0) w.y = -w.y;
                v[t] = cmulf(v[t], w);
            }
        }
        float2 o[R];
        if (R == 8) dif8<DIR>(v, o); else dif4<DIR>(v, o);
        const int idxD = (j / Ns) * (Ns * R) + (j & (Ns - 1));
        #pragma unroll
        for (int t = 0; t < R; t++) out[NPAD(idxD + t * Ns)] = o[t];
    }
}

// ---------------------------------------------------------------------------
__global__ void k_build_tw() {
    int q = blockIdx.x * blockDim.x + threadIdx.x;
    if (q < 2048) {
        float a = (float)q * (1.0f / 1024.0f);
        g_tw[q] = make_float2(cospif(a), -sinpif(a));
        float p = (float)q * (1.0f / 4096.0f);
        g_ph[q] = make_float2(cospif(p), sinpif(p));
    }
}

// ---------------------------------------------------------------------------
#define C_K0  0.0220970869120796f   // 1/sqrt(2048)
#define C_KS  0.015625f             // 1/64
#define W_0   0.0220970869120796f
#define W_K   0.03125f
#define SQRT2 1.41421356237309505f

// packed idct spectrum element, computed straight from sarr
__device__ __forceinline__ float2 zval(const float* __restrict__ sarr, int q) {
    float2 Vq, Vh;
    if (q == 0) {
        Vq = make_float2(sarr[0] * C_K0, 0.0f);
        Vh = make_float2(SQRT2 * sarr[H_H] * C_KS, 0.0f);
    } else {
        float Xq  = sarr[q] * C_KS;
        float Xnq = sarr[N_N - q] * C_KS;
        float2 p  = g_ph[q];
        Vq = make_float2(p.x * Xq + p.y * Xnq, p.y * Xq - p.x * Xnq);
        float Xh  = sarr[q + H_H] * C_KS;
        float Xhq = sarr[H_H - q] * C_KS;
        float2 p2 = g_ph[q + H_H];
        Vh = make_float2(p2.x * Xh + p2.y * Xhq, p2.y * Xh - p2.x * Xhq);
    }
    float2 sum = cadd(Vq, Vh);
    float2 dif = csub(Vq, Vh);
    float2 tw  = g_tw[q];
    float2 e   = make_float2(tw.x * dif.x + tw.y * dif.y,
                             tw.x * dif.y - tw.y * dif.x);   // conj(tw)*dif
    return make_float2(sum.x - e.y, sum.y + e.x);            // sum + i*e
}

// IFFT stage 1 (R=8, Ns=1, DIR=+1) fused with Z construction (j = tid, one pass)
__device__ __forceinline__ void ifft_stage1_fromS(const float* __restrict__ sarr,
                                                  float2* __restrict__ out, int tid) {
    float2 v[8];
    #pragma unroll
    for (int t = 0; t < 8; t++) v[t] = zval(sarr, tid + t * 128);
    float2 o[8];
    dif8<1>(v, o);
    const int idxD = tid * 8;
    #pragma unroll
    for (int t = 0; t < 8; t++) out[NPAD(idxD + t)] = o[t];
}

// remaining 3 IFFT stages (8,4,4):  A -> B -> A -> B  (result in B)
__device__ __forceinline__ void ifft_tail(float2* A, float2* B, int tid) {
    fft_stage<8, 8,   1>(A, B, tid); __syncthreads();
    fft_stage<4, 64,  1>(B, A, tid); __syncthreads();
    fft_stage<4, 256, 1>(A, B, tid); __syncthreads();
}

// ---------------------------------------------------------------------------
__global__ void __launch_bounds__(128) solver(
    const float* __restrict__ x, const void* __restrict__ idxs,
    float* __restrict__ out)
{
    __shared__ float2 bufA[BUFSZ];
    __shared__ float2 bufB[BUFSZ];
    __shared__ float2 bufC[BUFSZ];   // scatter-only buffer: zeroed ONCE
    __shared__ float  sarr[N_N];

    const int tid = threadIdx.x;
    const int sig = blockIdx.x;
    const float* xs = x + (size_t)sig * N_N;

    // per-thread measurement registers + one-time bufC zero + s=0
    int   nmr[4];
    float bmr[4];
    #pragma unroll
    for (int u = 0; u < 4; u++) {
        int m = tid + u * 128;
        int j = get_idx(idxs, m);
        bmr[u] = xs[j] * 100.0f;
        nmr[u] = (j & 1) ? (2047 - ((j - 1) >> 1)) : (j >> 1);
    }
    for (int i = tid; i < BUFSZ; i += 128) bufC[i] = make_float2(0.f, 0.f);
    for (int k = tid; k < N_N; k += 128) sarr[k] = 0.0f;
    __syncthreads();

    for (int it = 0; it < NITER; it++) {
        // ---- idct: fused Z-build + 4-stage IFFT -> z in bufB ----
        ifft_stage1_fromS(sarr, bufA, tid); __syncthreads();
        ifft_tail(bufA, bufB, tid);

        // ---- gather residual from z (bufB); scatter into clean bufC ----
        #pragma unroll
        for (int u = 0; u < 4; u++) {
            int p = nmr[u];
            float2 zv = bufB[NPAD(p >> 1)];
            float r = ((p & 1) ? zv.y : zv.x) - bmr[u];
            ((float*)bufC)[2 * NPAD(p >> 1) + (p & 1)] = r;
        }
        __syncthreads();

        // ---- dct: 4-stage forward FFT of packed residual -> bufB ----
        fft_stage<8, 1,   -1>(bufC, bufA, tid); __syncthreads();
        fft_stage<8, 8,   -1>(bufA, bufB, tid); __syncthreads();
        fft_stage<4, 64,  -1>(bufB, bufA, tid); __syncthreads();
        fft_stage<4, 256, -1>(bufA, bufB, tid); __syncthreads();

        // ---- unpack + dct post + ISTA update (pairs k=q, N-q) ----
        for (int q = tid; q < H_H; q += 128) {
            if (q == 0) {
                float2 Z0 = bufB[NPAD(0)];
                float v0 = Z0.x + Z0.y;
                float vh = Z0.x - Z0.y;
                float g0 = W_0 * v0;
                float gh = W_K * (g_ph[H_H].x * vh);
                float u0 = sarr[0] - g0;
                float t0 = fabsf(u0) - 0.05f;
                sarr[0] = (t0 > 0.0f) ? copysignf(t0, u0) : 0.0f;
                float uh = sarr[H_H] - gh;
                float th = fabsf(uh) - 0.05f;
                sarr[H_H] = (th > 0.0f) ? copysignf(th, uh) : 0.0f;
            } else {
                float2 Zq = bufB[NPAD(q)];
                float2 Zr = bufB[NPAD(H_H - q)];
                float2 Zm = make_float2(Zr.x, -Zr.y);
                float2 Es = make_float2(0.5f * (Zq.x + Zm.x),
                                        0.5f * (Zq.y + Zm.y));
                float2 Os = csub(Zq, Zm);
                float2 t  = cmulf(g_tw[q], Os);
                float2 V  = make_float2(Es.x + 0.5f * t.y,
                                        Es.y - 0.5f * t.x);
                float2 p1 = g_ph[q];
                float Xq  = p1.x * V.x + p1.y * V.y;
                float2 p2 = g_ph[N_N - q];
                float Xnq = p2.x * V.x - p2.y * V.y;
                float uq = sarr[q] - W_K * Xq;
                float tq = fabsf(uq) - 0.05f;
                sarr[q] = (tq > 0.0f) ? copysignf(tq, uq) : 0.0f;
                float un = sarr[N_N - q] - W_K * Xnq;
                float tn = fabsf(un) - 0.05f;
                sarr[N_N - q] = (tn > 0.0f) ? copysignf(tn, un) : 0.0f;
            }
        }
        __syncthreads();
    }

    // ---- final: y = idct(s) / 100 ----
    ifft_stage1_fromS(sarr, bufA, tid); __syncthreads();
    ifft_tail(bufA, bufB, tid);

    float* os = out + (size_t)sig * N_N;
    for (int j = tid; j < N_N; j += 128) {
        float2 zv = bufB[NPAD(j >> 1)];
        float v = (j & 1) ? zv.y : zv.x;
        int o = (j < H_H) ? (2 * j) : (2 * (2047 - j) + 1);
        os[o] = v * 0.01f;
    }
}

extern "C" void kernel_launch(void* const* d_in, const int* in_sizes, int n_in,
                              void* d_out, int out_size) {
    const float* x    = (const float*)d_in[0];
    const void*  idxs = d_in[1];
    float*       out  = (float*)d_out;

    k_build_tw<<<(2048 + 255) / 256, 256>>>();
    solver<<<B_I, 128>>>(x, idxs, out);
}

// round 16
// speedup vs baseline: 2.5180x; 1.6639x over previous
#include <cuda_runtime.h>
#include <cstdint>

#define B_I   3072
#define N_N   2048
#define H_H   1024
#define M_M   512
#define NITER 100
#define TH    64      // threads per CTA (one signal per CTA)

// bank-conflict padding: one extra float2 per 16
#define NPAD(i) ((i) + ((i) >> 4))
#define BUFSZ 1088   // NPAD(1023)=1086

// twiddle tables
__device__ float2 g_tw[2048];   // e^{-2*pi*i*q/2048}
__device__ float2 g_ph[2048];   // e^{+i*pi*k/4096}

// ---------------------------------------------------------------------------
__device__ __forceinline__ float2 cadd(float2 a, float2 b) {
    return make_float2(a.x + b.x, a.y + b.y);
}
__device__ __forceinline__ float2 csub(float2 a, float2 b) {
    return make_float2(a.x - b.x, a.y - b.y);
}
__device__ __forceinline__ float2 cmulf(float2 a, float2 b) {
    return make_float2(a.x * b.x - a.y * b.y, a.x * b.y + a.y * b.x);
}
template<int DIR>
__device__ __forceinline__ float2 rotd(float2 v) {   // multiply by DIR*i
    return (DIR < 0) ? make_float2(v.y, -v.x) : make_float2(-v.y, v.x);
}

__device__ __forceinline__ int get_idx(const void* idxp, int m) {
    const long long* p64 = (const long long*)idxp;
    if ((p64[0] >> 32) == 0LL) return (int)p64[m];
    return ((const int*)idxp)[m];
}

// ---------------------------------------------------------------------------
template<int DIR>
__device__ __forceinline__ void dif8(const float2 v[8], float2 o[8]) {
    const float r = 0.70710678118654752f;
    float2 s0 = cadd(v[0], v[4]), s1 = cadd(v[1], v[5]);
    float2 s2 = cadd(v[2], v[6]), s3 = cadd(v[3], v[7]);
    float2 d0 = csub(v[0], v[4]);
    float2 d1 = csub(v[1], v[5]);
    float2 d2 = csub(v[2], v[6]);
    float2 d3 = csub(v[3], v[7]);
    if (DIR < 0) {
        d1 = make_float2(r * (d1.x + d1.y), r * (d1.y - d1.x));
        d2 = make_float2(d2.y, -d2.x);
        d3 = make_float2(r * (d3.y - d3.x), -r * (d3.x + d3.y));
    } else {
        d1 = make_float2(r * (d1.x - d1.y), r * (d1.y + d1.x));
        d2 = make_float2(-d2.y, d2.x);
        d3 = make_float2(-r * (d3.x + d3.y), r * (d3.x - d3.y));
    }
    float2 a0 = cadd(s0, s2), b0 = csub(s0, s2);
    float2 a1 = cadd(s1, s3), b1 = rotd<DIR>(csub(s1, s3));
    o[0] = cadd(a0, a1);
    o[4] = csub(a0, a1);
    o[2] = cadd(b0, b1);
    o[6] = csub(b0, b1);
    float2 c0 = cadd(d0, d2), e0 = csub(d0, d2);
    float2 c1 = cadd(d1, d3), e1 = rotd<DIR>(csub(d1, d3));
    o[1] = cadd(c0, c1);
    o[5] = csub(c0, c1);
    o[3] = cadd(e0, e1);
    o[7] = csub(e0, e1);
}

template<int DIR>
__device__ __forceinline__ void dif4(const float2 v[4], float2 o[4]) {
    float2 a0 = cadd(v[0], v[2]), b0 = csub(v[0], v[2]);
    float2 a1 = cadd(v[1], v[3]), b1 = rotd<DIR>(csub(v[1], v[3]));
    o[0] = cadd(a0, a1);
    o[2] = csub(a0, a1);
    o[1] = cadd(b0, b1);
    o[3] = csub(b0, b1);
}

// W16^e multiply (forward table; DIR>0 conjugates).  e in {0,1,2,3,4,6,9}.
template<int DIR>
__device__ __forceinline__ float2 w16mul(float2 a, int e) {
    const float C1 = 0.92387953251128675f, S1 = 0.38268343236508977f;
    const float R_ = 0.70710678118654752f;
    float c, s;
    switch (e) {
        case 0: return a;
        case 1: c =  C1; s = -S1; break;
        case 2: c =  R_; s = -R_; break;
        case 3: c =  S1; s = -C1; break;
        case 4: c = 0.f; s = -1.f; break;
        case 6: c = -R_; s = -R_; break;
        default: c = -C1; s =  S1; break;   // e == 9
    }
    if (DIR > 0) s = -s;
    return make_float2(a.x * c - a.y * s, a.x * s + a.y * c);
}

// ---------------------------------------------------------------------------
// Stockham stage, 1024-pt, radix 8, 64 threads (2 iterations).
// Twiddles: one table load, powers by chained multiplication.
// ---------------------------------------------------------------------------
template<int Ns, int DIR>
__device__ __forceinline__ void fft_stage8(const float2* __restrict__ in,
                                           float2* __restrict__ out, int t64) {
    constexpr int NB  = 128;                // 1024/8
    constexpr int TWF = 2048 / (Ns * 8);
    #pragma unroll
    for (int jj = 0; jj < 2; jj++) {
        const int j = t64 + jj * TH;
        float2 v[8];
        #pragma unroll
        for (int t = 0; t < 8; t++) v[t] = in[NPAD(j + t * NB)];
        if (Ns > 1) {
            float2 w1 = g_tw[(j & (Ns - 1)) * TWF];
            if (DIR > 0) w1.y = -w1.y;
            float2 wr = w1;
            v[1] = cmulf(v[1], wr);
            #pragma unroll
            for (int t = 2; t < 8; t++) {
                wr = cmulf(wr, w1);
                v[t] = cmulf(v[t], wr);
            }
        }
        float2 o[8];
        dif8<DIR>(v, o);
        const int idxD = (j / Ns) * (Ns * 8) + (j & (Ns - 1));
        #pragma unroll
        for (int t = 0; t < 8; t++) out[NPAD(idxD + t * Ns)] = o[t];
    }
}

// radix-16 final stage (Ns=64): in-place two radix-4 layers, 64 threads,
// 1 butterfly/thread, immediate stores.
template<int DIR>
__device__ __forceinline__ void fft_stage16(const float2* __restrict__ in,
                                            float2* __restrict__ out, int t64) {
    const int j = t64;                      // NB = 64
    float2 x[16];
    #pragma unroll
    for (int t = 0; t < 16; t++) x[t] = in[NPAD(j + t * 64)];
    {
        float2 w1 = g_tw[(j & 63) * 2];     // TWF = 2048/(64*16) = 2
        if (DIR > 0) w1.y = -w1.y;
        float2 wr = w1;
        x[1] = cmulf(x[1], wr);
        #pragma unroll
        for (int t = 2; t < 16; t++) {
            wr = cmulf(wr, w1);
            x[t] = cmulf(x[t], wr);
        }
    }
    // layer A: dif4 over m on slots r+4m, results back into slots r+4q
    #pragma unroll
    for (int r = 0; r < 4; r++) {
        float2 a[4] = { x[r], x[r + 4], x[r + 8], x[r + 12] };
        float2 b[4];
        dif4<DIR>(a, b);
        x[r] = b[0]; x[r + 4] = b[1]; x[r + 8] = b[2]; x[r + 12] = b[3];
    }
    // layer B: twiddle + dif4 over r, store X[q+4p]
    #pragma unroll
    for (int q = 0; q < 4; q++) {
        float2 u[4];
        u[0] = x[4 * q];
        u[1] = w16mul<DIR>(x[4 * q + 1], q);
        u[2] = w16mul<DIR>(x[4 * q + 2], 2 * q);
        u[3] = w16mul<DIR>(x[4 * q + 3], 3 * q);
        float2 y[4];
        dif4<DIR>(u, y);
        #pragma unroll
        for (int p = 0; p < 4; p++)
            out[NPAD(j + (q + 4 * p) * 64)] = y[p];
    }
}

// ---------------------------------------------------------------------------
__global__ void k_build_tw() {
    int q = blockIdx.x * blockDim.x + threadIdx.x;
    if (q < 2048) {
        float a = (float)q * (1.0f / 1024.0f);
        g_tw[q] = make_float2(cospif(a), -sinpif(a));
        float p = (float)q * (1.0f / 4096.0f);
        g_ph[q] = make_float2(cospif(p), sinpif(p));
    }
}

// ---------------------------------------------------------------------------
#define C_K0  0.0220970869120796f   // 1/sqrt(2048)
#define C_KS  0.015625f             // 1/64
#define W_0   0.0220970869120796f
#define W_K   0.03125f
#define SQRT2 1.41421356237309505f
#define RHALF 0.70710678118654752f

// packed idct spectrum element; ph[q+1024] derived from ph[q] (no 2nd load)
__device__ __forceinline__ float2 zval(const float* __restrict__ sarr, int q) {
    float2 Vq, Vh;
    if (q == 0) {
        Vq = make_float2(sarr[0] * C_K0, 0.0f);
        Vh = make_float2(SQRT2 * sarr[H_H] * C_KS, 0.0f);
    } else {
        float Xq  = sarr[q] * C_KS;
        float Xnq = sarr[N_N - q] * C_KS;
        float2 p  = g_ph[q];
        Vq = make_float2(p.x * Xq + p.y * Xnq, p.y * Xq - p.x * Xnq);
        float Xh  = sarr[q + H_H] * C_KS;
        float Xhq = sarr[H_H - q] * C_KS;
        float2 p2 = make_float2(RHALF * (p.x - p.y), RHALF * (p.x + p.y));
        Vh = make_float2(p2.x * Xh + p2.y * Xhq, p2.y * Xh - p2.x * Xhq);
    }
    float2 sum = cadd(Vq, Vh);
    float2 dif = csub(Vq, Vh);
    float2 tw  = g_tw[q];
    float2 e   = make_float2(tw.x * dif.x + tw.y * dif.y,
                             tw.x * dif.y - tw.y * dif.x);   // conj(tw)*dif
    return make_float2(sum.x - e.y, sum.y + e.x);            // sum + i*e
}

// IFFT stage 1 (R=8, Ns=1, DIR=+1) fused with Z construction, 2 iterations
__device__ __forceinline__ void ifft_stage1_fromS(const float* __restrict__ sarr,
                                                  float2* __restrict__ out, int t64) {
    #pragma unroll
    for (int jj = 0; jj < 2; jj++) {
        const int j = t64 + jj * TH;
        float2 v[8];
        #pragma unroll
        for (int t = 0; t < 8; t++) v[t] = zval(sarr, j + t * 128);
        float2 o[8];
        dif8<1>(v, o);
        #pragma unroll
        for (int t = 0; t < 8; t++) out[NPAD(j * 8 + t)] = o[t];
    }
}

// ---------------------------------------------------------------------------
__global__ void __launch_bounds__(TH) solver(
    const float* __restrict__ x, const void* __restrict__ idxs,
    float* __restrict__ out)
{
    __shared__ float2 bufA[BUFSZ];
    __shared__ float2 bufB[BUFSZ];
    __shared__ float2 bufC[BUFSZ];   // scatter-only buffer: zeroed ONCE
    __shared__ float  sarr[N_N];

    const int t64 = threadIdx.x;
    const int sig = blockIdx.x;
    const float* xs = x + (size_t)sig * N_N;

    // measurement registers (8/thread) + one-time bufC zero + s=0
    int   nmr[8];
    float bmr[8];
    #pragma unroll
    for (int u = 0; u < 8; u++) {
        int m = t64 + u * TH;
        int j = get_idx(idxs, m);
        bmr[u] = xs[j] * 100.0f;
        nmr[u] = (j & 1) ? (2047 - ((j - 1) >> 1)) : (j >> 1);
    }
    for (int i = t64; i < BUFSZ; i += TH) bufC[i] = make_float2(0.f, 0.f);
    for (int k = t64; k < N_N; k += TH) sarr[k] = 0.0f;
    __syncthreads();

    for (int it = 0; it < NITER; it++) {
        // ---- idct: fused Z-build + 3-stage IFFT (8,8,16) -> z in bufA ----
        ifft_stage1_fromS(sarr, bufA, t64);   __syncthreads();
        fft_stage8<8, 1>(bufA, bufB, t64);    __syncthreads();
        fft_stage16<1>(bufB, bufA, t64);      __syncthreads();

        // ---- gather residual from z (bufA); scatter into clean bufC ----
        #pragma unroll
        for (int u = 0; u < 8; u++) {
            int p = nmr[u];
            float2 zv = bufA[NPAD(p >> 1)];
            float r = ((p & 1) ? zv.y : zv.x) - bmr[u];
            ((float*)bufC)[2 * NPAD(p >> 1) + (p & 1)] = r;
        }
        __syncthreads();

        // ---- dct: 3-stage forward FFT (8,8,16) -> spectrum in bufA ----
        fft_stage8<1, -1>(bufC, bufB, t64);   __syncthreads();
        fft_stage8<8, -1>(bufB, bufC, t64);   __syncthreads();
        // NOTE: bufC is used as intermediate here, then restored below!
        fft_stage16<-1>(bufC, bufA, t64);     __syncthreads();

        // restore bufC cleanliness: re-zero only the slots stage2 wrote?
        // stage2 wrote ALL slots -> must re-zero whole buffer... instead,
        // swap roles: zero only the scattered slots (cheap, 8/thread).
        #pragma unroll
        for (int u = 0; u < 8; u++) {
            int p = nmr[u];
            ((float*)bufC)[2 * NPAD(p >> 1) + (p & 1)] = 0.0f;
        }
        // full clean needed because stage2 dirtied everything:
        for (int i = t64; i < BUFSZ; i += TH) bufC[i] = make_float2(0.f, 0.f);

        // ---- unpack + dct post + ISTA update (pairs k=q, N-q) ----
        for (int q = t64; q < H_H; q += TH) {
            if (q == 0) {
                float2 Z0 = bufA[NPAD(0)];
                float v0 = Z0.x + Z0.y;
                float vh = Z0.x - Z0.y;
                float g0 = W_0 * v0;
                float gh = W_K * (RHALF * vh);
                float u0 = sarr[0] - g0;
                float t0 = fabsf(u0) - 0.05f;
                sarr[0] = (t0 > 0.0f) ? copysignf(t0, u0) : 0.0f;
                float uh = sarr[H_H] - gh;
                float th = fabsf(uh) - 0.05f;
                sarr[H_H] = (th > 0.0f) ? copysignf(th, uh) : 0.0f;
            } else {
                float2 Zq = bufA[NPAD(q)];
                float2 Zr = bufA[NPAD(H_H - q)];
                float2 Zm = make_float2(Zr.x, -Zr.y);
                float2 Es = make_float2(0.5f * (Zq.x + Zm.x),
                                        0.5f * (Zq.y + Zm.y));
                float2 Os = csub(Zq, Zm);
                float2 t  = cmulf(g_tw[q], Os);
                float2 V  = make_float2(Es.x + 0.5f * t.y,
                                        Es.y - 0.5f * t.x);
                float2 p1 = g_ph[q];
                float Xq  = p1.x * V.x + p1.y * V.y;
                float Xnq = p1.y * V.x - p1.x * V.y;   // ph[N-q] = i*conj(p1)
                float uq = sarr[q] - W_K * Xq;
                float tq = fabsf(uq) - 0.05f;
                sarr[q] = (tq > 0.0f) ? copysignf(tq, uq) : 0.0f;
                float un = sarr[N_N - q] - W_K * Xnq;
                float tn = fabsf(un) - 0.05f;
                sarr[N_N - q] = (tn > 0.0f) ? copysignf(tn, un) : 0.0f;
            }
        }
        __syncthreads();
    }

    // ---- final: y = idct(s) / 100 ----
    ifft_stage1_fromS(sarr, bufA, t64);   __syncthreads();
    fft_stage8<8, 1>(bufA, bufB, t64);    __syncthreads();
    fft_stage16<1>(bufB, bufA, t64);      __syncthreads();

    float* os = out + (size_t)sig * N_N;
    for (int j = t64; j < N_N; j += TH) {
        float2 zv = bufA[NPAD(j >> 1)];
        float v = (j & 1) ? zv.y : zv.x;
        int o = (j < H_H) ? (2 * j) : (2 * (2047 - j) + 1);
        os[o] = v * 0.01f;
    }
}

extern "C" void kernel_launch(void* const* d_in, const int* in_sizes, int n_in,
                              void* d_out, int out_size) {
    const float* x    = (const float*)d_in[0];
    const void*  idxs = d_in[1];
    float*       out  = (float*)d_out;

    k_build_tw<<<(2048 + 255) / 256, 256>>>();
    solver<<<B_I, TH>>>(x, idxs, out);
}

// round 17
// speedup vs baseline: 2.7069x; 1.0750x over previous
#include <cuda_runtime.h>
#include <cstdint>

#define B_I   3072
#define N_N   2048
#define H_H   1024
#define M_M   512
#define NITER 100
#define TH    64      // threads per CTA (one signal per CTA)

// bank-conflict padding: one extra float2 per 16
#define NPAD(i) ((i) + ((i) >> 4))
#define BUFSZ 1088   // NPAD(1023)=1086

// twiddle tables
__device__ float2 g_tw[2048];   // e^{-2*pi*i*q/2048}
__device__ float2 g_ph[2048];   // e^{+i*pi*k/4096}

// ---------------------------------------------------------------------------
__device__ __forceinline__ float2 cadd(float2 a, float2 b) {
    return make_float2(a.x + b.x, a.y + b.y);
}
__device__ __forceinline__ float2 csub(float2 a, float2 b) {
    return make_float2(a.x - b.x, a.y - b.y);
}
__device__ __forceinline__ float2 cmulf(float2 a, float2 b) {
    return make_float2(a.x * b.x - a.y * b.y, a.x * b.y + a.y * b.x);
}
template<int DIR>
__device__ __forceinline__ float2 rotd(float2 v) {   // multiply by DIR*i
    return (DIR < 0) ? make_float2(v.y, -v.x) : make_float2(-v.y, v.x);
}

__device__ __forceinline__ int get_idx(const void* idxp, int m) {
    const long long* p64 = (const long long*)idxp;
    if ((p64[0] >> 32) == 0LL) return (int)p64[m];
    return ((const int*)idxp)[m];
}

// ---------------------------------------------------------------------------
template<int DIR>
__device__ __forceinline__ void dif8(const float2 v[8], float2 o[8]) {
    const float r = 0.70710678118654752f;
    float2 s0 = cadd(v[0], v[4]), s1 = cadd(v[1], v[5]);
    float2 s2 = cadd(v[2], v[6]), s3 = cadd(v[3], v[7]);
    float2 d0 = csub(v[0], v[4]);
    float2 d1 = csub(v[1], v[5]);
    float2 d2 = csub(v[2], v[6]);
    float2 d3 = csub(v[3], v[7]);
    if (DIR < 0) {
        d1 = make_float2(r * (d1.x + d1.y), r * (d1.y - d1.x));
        d2 = make_float2(d2.y, -d2.x);
        d3 = make_float2(r * (d3.y - d3.x), -r * (d3.x + d3.y));
    } else {
        d1 = make_float2(r * (d1.x - d1.y), r * (d1.y + d1.x));
        d2 = make_float2(-d2.y, d2.x);
        d3 = make_float2(-r * (d3.x + d3.y), r * (d3.x - d3.y));
    }
    float2 a0 = cadd(s0, s2), b0 = csub(s0, s2);
    float2 a1 = cadd(s1, s3), b1 = rotd<DIR>(csub(s1, s3));
    o[0] = cadd(a0, a1);
    o[4] = csub(a0, a1);
    o[2] = cadd(b0, b1);
    o[6] = csub(b0, b1);
    float2 c0 = cadd(d0, d2), e0 = csub(d0, d2);
    float2 c1 = cadd(d1, d3), e1 = rotd<DIR>(csub(d1, d3));
    o[1] = cadd(c0, c1);
    o[5] = csub(c0, c1);
    o[3] = cadd(e0, e1);
    o[7] = csub(e0, e1);
}

template<int DIR>
__device__ __forceinline__ void dif4(const float2 v[4], float2 o[4]) {
    float2 a0 = cadd(v[0], v[2]), b0 = csub(v[0], v[2]);
    float2 a1 = cadd(v[1], v[3]), b1 = rotd<DIR>(csub(v[1], v[3]));
    o[0] = cadd(a0, a1);
    o[2] = csub(a0, a1);
    o[1] = cadd(b0, b1);
    o[3] = csub(b0, b1);
}

// W16^e multiply (forward table; DIR>0 conjugates).  e in {0,1,2,3,4,6,9}.
template<int DIR>
__device__ __forceinline__ float2 w16mul(float2 a, int e) {
    const float C1 = 0.92387953251128675f, S1 = 0.38268343236508977f;
    const float R_ = 0.70710678118654752f;
    float c, s;
    switch (e) {
        case 0: return a;
        case 1: c =  C1; s = -S1; break;
        case 2: c =  R_; s = -R_; break;
        case 3: c =  S1; s = -C1; break;
        case 4: c = 0.f; s = -1.f; break;
        case 6: c = -R_; s = -R_; break;
        default: c = -C1; s =  S1; break;   // e == 9
    }
    if (DIR > 0) s = -s;
    return make_float2(a.x * c - a.y * s, a.x * s + a.y * c);
}

// ---------------------------------------------------------------------------
// Stockham stage, 1024-pt, radix 8, 64 threads (2 iterations).
// Twiddles: one table load, powers by chained multiplication.
// ---------------------------------------------------------------------------
template<int Ns, int DIR>
__device__ __forceinline__ void fft_stage8(const float2* __restrict__ in,
                                           float2* __restrict__ out, int t64) {
    constexpr int NB  = 128;                // 1024/8
    constexpr int TWF = 2048 / (Ns * 8);
    #pragma unroll
    for (int jj = 0; jj < 2; jj++) {
        const int j = t64 + jj * TH;
        float2 v[8];
        #pragma unroll
        for (int t = 0; t < 8; t++) v[t] = in[NPAD(j + t * NB)];
        if (Ns > 1) {
            float2 w1 = g_tw[(j & (Ns - 1)) * TWF];
            if (DIR > 0) w1.y = -w1.y;
            float2 wr = w1;
            v[1] = cmulf(v[1], wr);
            #pragma unroll
            for (int t = 2; t < 8; t++) {
                wr = cmulf(wr, w1);
                v[t] = cmulf(v[t], wr);
            }
        }
        float2 o[8];
        dif8<DIR>(v, o);
        const int idxD = (j / Ns) * (Ns * 8) + (j & (Ns - 1));
        #pragma unroll
        for (int t = 0; t < 8; t++) out[NPAD(idxD + t * Ns)] = o[t];
    }
}

// radix-16 final stage (Ns=64): in-place two radix-4 layers, 64 threads,
// 1 butterfly/thread, immediate stores.
template<int DIR>
__device__ __forceinline__ void fft_stage16(const float2* __restrict__ in,
                                            float2* __restrict__ out, int t64) {
    const int j = t64;                      // NB = 64
    float2 x[16];
    #pragma unroll
    for (int t = 0; t < 16; t++) x[t] = in[NPAD(j + t * 64)];
    {
        float2 w1 = g_tw[(j & 63) * 2];     // TWF = 2048/(64*16) = 2
        if (DIR > 0) w1.y = -w1.y;
        float2 wr = w1;
        x[1] = cmulf(x[1], wr);
        #pragma unroll
        for (int t = 2; t < 16; t++) {
            wr = cmulf(wr, w1);
            x[t] = cmulf(x[t], wr);
        }
    }
    // layer A: dif4 over m on slots r+4m, results back into slots r+4q
    #pragma unroll
    for (int r = 0; r < 4; r++) {
        float2 a[4] = { x[r], x[r + 4], x[r + 8], x[r + 12] };
        float2 b[4];
        dif4<DIR>(a, b);
        x[r] = b[0]; x[r + 4] = b[1]; x[r + 8] = b[2]; x[r + 12] = b[3];
    }
    // layer B: twiddle + dif4 over r, store X[q+4p]
    #pragma unroll
    for (int q = 0; q < 4; q++) {
        float2 u[4];
        u[0] = x[4 * q];
        u[1] = w16mul<DIR>(x[4 * q + 1], q);
        u[2] = w16mul<DIR>(x[4 * q + 2], 2 * q);
        u[3] = w16mul<DIR>(x[4 * q + 3], 3 * q);
        float2 y[4];
        dif4<DIR>(u, y);
        #pragma unroll
        for (int p = 0; p < 4; p++)
            out[NPAD(j + (q + 4 * p) * 64)] = y[p];
    }
}

// ---------------------------------------------------------------------------
__global__ void k_build_tw() {
    int q = blockIdx.x * blockDim.x + threadIdx.x;
    if (q < 2048) {
        float a = (float)q * (1.0f / 1024.0f);
        g_tw[q] = make_float2(cospif(a), -sinpif(a));
        float p = (float)q * (1.0f / 4096.0f);
        g_ph[q] = make_float2(cospif(p), sinpif(p));
    }
}

// ---------------------------------------------------------------------------
#define C_K0  0.0220970869120796f   // 1/sqrt(2048)
#define C_KS  0.015625f             // 1/64
#define W_0   0.0220970869120796f
#define W_K   0.03125f
#define SQRT2 1.41421356237309505f
#define RHALF 0.70710678118654752f

// packed idct spectrum element; ph[q+1024] derived from ph[q] (no 2nd load)
__device__ __forceinline__ float2 zval(const float* __restrict__ sarr, int q) {
    float2 Vq, Vh;
    if (q == 0) {
        Vq = make_float2(sarr[0] * C_K0, 0.0f);
        Vh = make_float2(SQRT2 * sarr[H_H] * C_KS, 0.0f);
    } else {
        float Xq  = sarr[q] * C_KS;
        float Xnq = sarr[N_N - q] * C_KS;
        float2 p  = g_ph[q];
        Vq = make_float2(p.x * Xq + p.y * Xnq, p.y * Xq - p.x * Xnq);
        float Xh  = sarr[q + H_H] * C_KS;
        float Xhq = sarr[H_H - q] * C_KS;
        float2 p2 = make_float2(RHALF * (p.x - p.y), RHALF * (p.x + p.y));
        Vh = make_float2(p2.x * Xh + p2.y * Xhq, p2.y * Xh - p2.x * Xhq);
    }
    float2 sum = cadd(Vq, Vh);
    float2 dif = csub(Vq, Vh);
    float2 tw  = g_tw[q];
    float2 e   = make_float2(tw.x * dif.x + tw.y * dif.y,
                             tw.x * dif.y - tw.y * dif.x);   // conj(tw)*dif
    return make_float2(sum.x - e.y, sum.y + e.x);            // sum + i*e
}

// IFFT stage 1 (R=8, Ns=1, DIR=+1) fused with Z construction, 2 iterations
__device__ __forceinline__ void ifft_stage1_fromS(const float* __restrict__ sarr,
                                                  float2* __restrict__ out, int t64) {
    #pragma unroll
    for (int jj = 0; jj < 2; jj++) {
        const int j = t64 + jj * TH;
        float2 v[8];
        #pragma unroll
        for (int t = 0; t < 8; t++) v[t] = zval(sarr, j + t * 128);
        float2 o[8];
        dif8<1>(v, o);
        #pragma unroll
        for (int t = 0; t < 8; t++) out[NPAD(j * 8 + t)] = o[t];
    }
}

// ---------------------------------------------------------------------------
__global__ void __launch_bounds__(TH) solver(
    const float* __restrict__ x, const void* __restrict__ idxs,
    float* __restrict__ out)
{
    __shared__ float2 bufA[BUFSZ];
    __shared__ float2 bufB[BUFSZ];
    __shared__ float2 bufC[BUFSZ];   // scatter-only buffer: NEVER dirtied
    __shared__ float  sarr[N_N];

    const int t64 = threadIdx.x;
    const int sig = blockIdx.x;
    const float* xs = x + (size_t)sig * N_N;

    // measurement registers (8/thread) + one-time bufC zero + s=0
    int   nmr[8];
    float bmr[8];
    #pragma unroll
    for (int u = 0; u < 8; u++) {
        int m = t64 + u * TH;
        int j = get_idx(idxs, m);
        bmr[u] = xs[j] * 100.0f;
        nmr[u] = (j & 1) ? (2047 - ((j - 1) >> 1)) : (j >> 1);
    }
    for (int i = t64; i < BUFSZ; i += TH) bufC[i] = make_float2(0.f, 0.f);
    for (int k = t64; k < N_N; k += TH) sarr[k] = 0.0f;
    __syncthreads();

    for (int it = 0; it < NITER; it++) {
        // ---- idct: fused Z-build + 3-stage IFFT (8,8,16) -> z in bufA ----
        ifft_stage1_fromS(sarr, bufA, t64);   __syncthreads();
        fft_stage8<8, 1>(bufA, bufB, t64);    __syncthreads();
        fft_stage16<1>(bufB, bufA, t64);      __syncthreads();

        // ---- gather residual from z (bufA); scatter into clean bufC ----
        // (scatter slots are identical every iteration -> plain overwrite)
        #pragma unroll
        for (int u = 0; u < 8; u++) {
            int p = nmr[u];
            float2 zv = bufA[NPAD(p >> 1)];
            float r = ((p & 1) ? zv.y : zv.x) - bmr[u];
            ((float*)bufC)[2 * NPAD(p >> 1) + (p & 1)] = r;
        }
        __syncthreads();

        // ---- dct: 3-stage forward FFT (8,8,16), bufC kept pristine ----
        // bufA (z) is dead after the gather -> use it as the intermediate.
        fft_stage8<1, -1>(bufC, bufB, t64);   __syncthreads();
        fft_stage8<8, -1>(bufB, bufA, t64);   __syncthreads();
        fft_stage16<-1>(bufA, bufB, t64);     __syncthreads();
        // spectrum in bufB

        // ---- unpack + dct post + ISTA update (pairs k=q, N-q) ----
        for (int q = t64; q < H_H; q += TH) {
            if (q == 0) {
                float2 Z0 = bufB[NPAD(0)];
                float v0 = Z0.x + Z0.y;
                float vh = Z0.x - Z0.y;
                float g0 = W_0 * v0;
                float gh = W_K * (RHALF * vh);
                float u0 = sarr[0] - g0;
                float t0 = fabsf(u0) - 0.05f;
                sarr[0] = (t0 > 0.0f) ? copysignf(t0, u0) : 0.0f;
                float uh = sarr[H_H] - gh;
                float th = fabsf(uh) - 0.05f;
                sarr[H_H] = (th > 0.0f) ? copysignf(th, uh) : 0.0f;
            } else {
                float2 Zq = bufB[NPAD(q)];
                float2 Zr = bufB[NPAD(H_H - q)];
                float2 Zm = make_float2(Zr.x, -Zr.y);
                float2 Es = make_float2(0.5f * (Zq.x + Zm.x),
                                        0.5f * (Zq.y + Zm.y));
                float2 Os = csub(Zq, Zm);
                float2 t  = cmulf(g_tw[q], Os);
                float2 V  = make_float2(Es.x + 0.5f * t.y,
                                        Es.y - 0.5f * t.x);
                float2 p1 = g_ph[q];
                float Xq  = p1.x * V.x + p1.y * V.y;
                float Xnq = p1.y * V.x - p1.x * V.y;   // ph[N-q] = i*conj(p1)
                float uq = sarr[q] - W_K * Xq;
                float tq = fabsf(uq) - 0.05f;
                sarr[q] = (tq > 0.0f) ? copysignf(tq, uq) : 0.0f;
                float un = sarr[N_N - q] - W_K * Xnq;
                float tn = fabsf(un) - 0.05f;
                sarr[N_N - q] = (tn > 0.0f) ? copysignf(tn, un) : 0.0f;
            }
        }
        __syncthreads();
    }

    // ---- final: y = idct(s) / 100 ----
    ifft_stage1_fromS(sarr, bufA, t64);   __syncthreads();
    fft_stage8<8, 1>(bufA, bufB, t64);    __syncthreads();
    fft_stage16<1>(bufB, bufA, t64);      __syncthreads();

    float* os = out + (size_t)sig * N_N;
    for (int j = t64; j < N_N; j += TH) {
        float2 zv = bufA[NPAD(j >> 1)];
        float v = (j & 1) ? zv.y : zv.x;
        int o = (j < H_H) ? (2 * j) : (2 * (2047 - j) + 1);
        os[o] = v * 0.01f;
    }
}

extern "C" void kernel_launch(void* const* d_in, const int* in_sizes, int n_in,
                              void* d_out, int out_size) {
    const float* x    = (const float*)d_in[0];
    const void*  idxs = d_in[1];
    float*       out  = (float*)d_out;

    k_build_tw<<<(2048 + 255) / 256, 256>>>();
    solver<<<B_I, TH>>>(x, idxs, out);
}